// round 4
// baseline (speedup 1.0000x reference)
#include <cuda_runtime.h>
#include <cuda_bf16.h>
#include <cuda_fp16.h>

#define NN 100000
#define NE 3200000
#define DD 128

#define SCAN_B 1024
#define NBLK ((NN + SCAN_B - 1) / SCAN_B)   // 98

// Scratch (__device__ globals — allocation-free rule)
__device__ int   g_deg[NN];          // zero-initialized at load; k_agg re-zeros after use
__device__ int   g_start[NN];
__device__ int   g_cursor[NN];
__device__ float g_dinv[NN];
__device__ int   g_bsum[NBLK];
__device__ int   g_boff[NBLK];
struct __align__(8) EdgeRec { int off; float n; };   // off = col * 256 (byte offset into g_xlh row)
__device__ EdgeRec g_edge[NE];
__device__ __half g_xlh[(size_t)NN * DD];            // fp16 transformed features

// ---------------------------------------------------------------- degree count (4 edges/thread)
// g_deg is guaranteed zero at entry: zero-init at module load, re-zeroed by k_agg each run.
__global__ void k_count(const int* __restrict__ row) {
    int t = blockIdx.x * blockDim.x + threadIdx.x;
    int e = t * 4;
    if (e + 4 <= NE) {
        int4 r4 = *(const int4*)&row[e];
        atomicAdd(&g_deg[r4.x], 1);
        atomicAdd(&g_deg[r4.y], 1);
        atomicAdd(&g_deg[r4.z], 1);
        atomicAdd(&g_deg[r4.w], 1);
    } else {
        for (int i = e; i < NE; i++) atomicAdd(&g_deg[row[i]], 1);
    }
}

// ---------------------------------------------------------------- scan stage 1: per-block sums
__global__ __launch_bounds__(SCAN_B) void k_scan1() {
    __shared__ int s[SCAN_B];
    int idx = blockIdx.x * SCAN_B + threadIdx.x;
    int v = (idx < NN) ? g_deg[idx] : 0;
    s[threadIdx.x] = v;
    __syncthreads();
    for (int off = SCAN_B / 2; off > 0; off >>= 1) {
        if (threadIdx.x < off) s[threadIdx.x] += s[threadIdx.x + off];
        __syncthreads();
    }
    if (threadIdx.x == 0) g_bsum[blockIdx.x] = s[0];
}

// ---------------------------------------------------------------- scan stage 2: scan block sums (1 block)
__global__ void k_scan2() {
    __shared__ int s[128];
    int t = threadIdx.x;
    int v = (t < NBLK) ? g_bsum[t] : 0;
    s[t] = v;
    __syncthreads();
    for (int off = 1; off < 128; off <<= 1) {
        int x = s[t];
        if (t >= off) x += s[t - off];
        __syncthreads();
        s[t] = x;
        __syncthreads();
    }
    if (t < NBLK) g_boff[t] = (t == 0) ? 0 : s[t - 1];
}

// ---------------------------------------------------------------- scan stage 3: local scan + offset + dinv
__global__ __launch_bounds__(SCAN_B) void k_scan3() {
    __shared__ int s[SCAN_B];
    int t = threadIdx.x;
    int idx = blockIdx.x * SCAN_B + t;
    int d = (idx < NN) ? g_deg[idx] : 0;
    s[t] = d;
    __syncthreads();
    for (int off = 1; off < SCAN_B; off <<= 1) {
        int x = s[t];
        if (t >= off) x += s[t - off];
        __syncthreads();
        s[t] = x;
        __syncthreads();
    }
    if (idx < NN) {
        int start = g_boff[blockIdx.x] + s[t] - d;   // exclusive
        g_start[idx]  = start;
        g_cursor[idx] = start;
        g_dinv[idx]   = (d > 0) ? rsqrtf((float)d) : 0.0f;
    }
}

// ---------------------------------------------------------------- CSR scatter, packed 8B record
__global__ void k_scatter(const int* __restrict__ row, const int* __restrict__ col) {
    int e = blockIdx.x * blockDim.x + threadIdx.x;
    if (e < NE) {
        int r = row[e];
        int c = col[e];
        int pos = atomicAdd(&g_cursor[r], 1);
        EdgeRec rec;
        rec.off = c << 8;                    // c * DD * sizeof(half) = c*256 byte offset
        rec.n   = g_dinv[r] * g_dinv[c];
        g_edge[pos] = rec;                   // single STG.64
    }
}

// ---------------------------------------------------------------- xl = x @ W^T + b  (f32x2 FMA, fp16 out)
#define BM 64
#define BK 32
__global__ __launch_bounds__(256) void k_gemm(const float* __restrict__ x,
                                              const float* __restrict__ W,
                                              const float* __restrict__ b) {
    __shared__ float Xs[BM][BK + 1];
    __shared__ float Wt[BK][132];

    int t  = threadIdx.x;
    int tx = t & 31;
    int ty = t >> 5;
    int row0 = blockIdx.x * BM;
    int n0 = tx * 4;

    unsigned long long acc[8][2];
#pragma unroll
    for (int i = 0; i < 8; i++) { acc[i][0] = 0ull; acc[i][1] = 0ull; }

    for (int k0 = 0; k0 < DD; k0 += BK) {
#pragma unroll
        for (int i = 0; i < 8; i++) {
            int m = ty + i * 8;
            int r = row0 + m;
            if (r >= NN) r = NN - 1;
            Xs[m][tx] = x[(size_t)r * DD + k0 + tx];
        }
#pragma unroll
        for (int i = 0; i < 16; i++) {
            int n = ty + i * 8;
            Wt[tx][n] = W[n * DD + k0 + tx];
        }
        __syncthreads();

#pragma unroll
        for (int kk = 0; kk < BK; kk++) {
            float4 wv = *(const float4*)&Wt[kk][n0];
            unsigned long long wxy, wzw;
            asm("mov.b64 %0, {%1, %2};" : "=l"(wxy) : "f"(wv.x), "f"(wv.y));
            asm("mov.b64 %0, {%1, %2};" : "=l"(wzw) : "f"(wv.z), "f"(wv.w));
#pragma unroll
            for (int i = 0; i < 8; i++) {
                float a = Xs[ty * 8 + i][kk];
                unsigned long long a2;
                asm("mov.b64 %0, {%1, %1};" : "=l"(a2) : "f"(a));
                asm("fma.rn.f32x2 %0, %1, %2, %0;" : "+l"(acc[i][0]) : "l"(a2), "l"(wxy));
                asm("fma.rn.f32x2 %0, %1, %2, %0;" : "+l"(acc[i][1]) : "l"(a2), "l"(wzw));
            }
        }
        __syncthreads();
    }

    float4 bias = *(const float4*)&b[n0];
#pragma unroll
    for (int i = 0; i < 8; i++) {
        int r = row0 + ty * 8 + i;
        if (r < NN) {
            float ax, ay, az, aw;
            asm("mov.b64 {%0, %1}, %2;" : "=f"(ax), "=f"(ay) : "l"(acc[i][0]));
            asm("mov.b64 {%0, %1}, %2;" : "=f"(az), "=f"(aw) : "l"(acc[i][1]));
            __half2 h0 = __floats2half2_rn(ax + bias.x, ay + bias.y);
            __half2 h1 = __floats2half2_rn(az + bias.z, aw + bias.w);
            uint2 o;
            o.x = *(unsigned int*)&h0;
            o.y = *(unsigned int*)&h1;
            *(uint2*)&g_xlh[(size_t)r * DD + n0] = o;
        }
    }
}

// ---------------------------------------------------------------- warp-per-node aggregation (fp16 gather)
// Lane owns columns lane*4..lane*4+3 (8 bytes). Byte offsets precomputed in records.
// 8-edge unroll -> 8 uint2 gathers in flight per warp per iteration.
#define AGG_FMA(P_OFF, P_N, Q, A)                                   \
    {                                                               \
        float nrm = __int_as_float(P_N);                            \
        float2 u = __half22float2(*(__half2*)&(Q).x);               \
        float2 v = __half22float2(*(__half2*)&(Q).y);               \
        (A).x += nrm * u.x; (A).y += nrm * u.y;                     \
        (A).z += nrm * v.x; (A).w += nrm * v.y;                     \
    }

__global__ __launch_bounds__(256) void k_agg(float* __restrict__ out) {
    int wid  = (blockIdx.x * blockDim.x + threadIdx.x) >> 5;
    int lane = threadIdx.x & 31;
    if (wid >= NN) return;

    int s = g_start[wid];
    int d = g_deg[wid];
    if (lane == 0) g_deg[wid] = 0;          // reset for next run (keeps k_count's precondition)

    const char* xb = (const char*)g_xlh + lane * 8;

    float4 a0 = make_float4(0.f, 0.f, 0.f, 0.f);
    float4 a1 = make_float4(0.f, 0.f, 0.f, 0.f);

    int j = 0;
    if ((s & 1) && d > 0) {                 // align record pointer to 16B
        EdgeRec e = g_edge[s];
        uint2 q = *(const uint2*)(xb + (unsigned)e.off);
        AGG_FMA(e.off, __float_as_int(e.n), q, a0);
        j = 1;
    }
    const int4* ep = (const int4*)&g_edge[s + j];

    for (; j + 8 <= d; j += 8) {
        int4 p0 = __ldg(&ep[0]);
        int4 p1 = __ldg(&ep[1]);
        int4 p2 = __ldg(&ep[2]);
        int4 p3 = __ldg(&ep[3]);
        ep += 4;
        uint2 q0 = *(const uint2*)(xb + (unsigned)p0.x);
        uint2 q1 = *(const uint2*)(xb + (unsigned)p0.z);
        uint2 q2 = *(const uint2*)(xb + (unsigned)p1.x);
        uint2 q3 = *(const uint2*)(xb + (unsigned)p1.z);
        uint2 q4 = *(const uint2*)(xb + (unsigned)p2.x);
        uint2 q5 = *(const uint2*)(xb + (unsigned)p2.z);
        uint2 q6 = *(const uint2*)(xb + (unsigned)p3.x);
        uint2 q7 = *(const uint2*)(xb + (unsigned)p3.z);
        AGG_FMA(p0.x, p0.y, q0, a0);
        AGG_FMA(p0.z, p0.w, q1, a1);
        AGG_FMA(p1.x, p1.y, q2, a0);
        AGG_FMA(p1.z, p1.w, q3, a1);
        AGG_FMA(p2.x, p2.y, q4, a0);
        AGG_FMA(p2.z, p2.w, q5, a1);
        AGG_FMA(p3.x, p3.y, q6, a0);
        AGG_FMA(p3.z, p3.w, q7, a1);
    }
    for (; j < d; j++) {
        EdgeRec e = g_edge[s + j];
        uint2 q = *(const uint2*)(xb + (unsigned)e.off);
        AGG_FMA(e.off, __float_as_int(e.n), q, a0);
    }

    float4 acc;
    acc.x = a0.x + a1.x;
    acc.y = a0.y + a1.y;
    acc.z = a0.z + a1.z;
    acc.w = a0.w + a1.w;
    *(float4*)&out[(size_t)wid * DD + lane * 4] = acc;   // coalesced 512B/warp
}

// ---------------------------------------------------------------- stream fork for GEMM overlap
static cudaStream_t g_s2;
static cudaEvent_t  g_evFork, g_evJoin;
static struct StreamInit {
    StreamInit() {
        cudaStreamCreateWithFlags(&g_s2, cudaStreamNonBlocking);
        cudaEventCreateWithFlags(&g_evFork, cudaEventDisableTiming);
        cudaEventCreateWithFlags(&g_evJoin, cudaEventDisableTiming);
    }
} g_streamInit;

// ---------------------------------------------------------------- launch
extern "C" void kernel_launch(void* const* d_in, const int* in_sizes, int n_in,
                              void* d_out, int out_size) {
    const float* x  = (const float*)d_in[0];
    const int*   ei = (const int*)d_in[1];
    const float* W  = (const float*)d_in[2];
    const float* b  = (const float*)d_in[3];
    float* out = (float*)d_out;

    const int* row = ei;
    const int* col = ei + NE;

    // Fork: GEMM on side stream, CSR build on main stream, join before agg.
    cudaEventRecord(g_evFork, 0);
    cudaStreamWaitEvent(g_s2, g_evFork, 0);
    k_gemm<<<(NN + BM - 1) / BM, 256, 0, g_s2>>>(x, W, b);
    cudaEventRecord(g_evJoin, g_s2);

    k_count  <<<(NE / 4 + 255) / 256, 256>>>(row);
    k_scan1  <<<NBLK, SCAN_B>>>();
    k_scan2  <<<1, 128>>>();
    k_scan3  <<<NBLK, SCAN_B>>>();
    k_scatter<<<(NE + 255) / 256, 256>>>(row, col);

    cudaStreamWaitEvent(0, g_evJoin, 0);
    k_agg    <<<((size_t)NN * 32 + 255) / 256, 256>>>(out);
}